// round 13
// baseline (speedup 1.0000x reference)
#include <cuda_runtime.h>
#include <cuda_fp16.h>
#include <cstdint>
#include <cstddef>

// Problem dims (fixed by the reference)
static constexpr int M_DIM  = 512;    // B*S
static constexpr int K_DIM  = 4096;   // IN
static constexpr int N_DIM  = 11008;  // OUT
static constexpr int MTILE  = 128;
static constexpr int NTILE  = 64;     // 2 CTAs/SM
static constexpr int KSLAB  = 64;     // K per pipeline slab
static constexpr int KSPLIT = 2;      // K-split (wave balancing)
static constexpr int KUNIT  = K_DIM / KSPLIT;    // 2048 k per CTA
static constexpr int NSLABS = KUNIT / KSLAB;     // 32 slabs per CTA
static constexpr int STAGES = 3;      // cp.async pipeline depth
static constexpr int THREADS = 256;   // 8 warps: 4(m) x 2(n), 32x32 each

// fp16 activations (exact GEMM except one f32->f16 rounding)
__device__ __half g_A[M_DIM * K_DIM];                     // 4 MB
// split-K raw partial accumulators (deterministic reduction, no atomics)
__device__ float  g_P[(size_t)KSPLIT * M_DIM * N_DIM];    // 45 MB

// ------------------------------------------------------------------ helpers
__device__ __forceinline__ uint32_t smem_u32(const void* p) {
    uint32_t r;
    asm("{ .reg .u64 t; cvta.to.shared.u64 t, %1; cvt.u32.u64 %0, t; }"
        : "=r"(r) : "l"(p));
    return r;
}

__device__ __forceinline__ uint32_t prmt(uint32_t a, uint32_t b, uint32_t s) {
    uint32_t r;
    asm("prmt.b32 %0, %1, %2, %3;" : "=r"(r) : "r"(a), "r"(b), "r"(s));
    return r;
}

__device__ __forceinline__ uint32_t hsub2(uint32_t a, uint32_t b) {
    uint32_t r;
    asm("sub.rn.f16x2 %0, %1, %2;" : "=r"(r) : "r"(a), "r"(b));
    return r;
}

// XOR swizzle on 128B rows (16B chunks) -> conflict-free ldmatrix
#define SWZ(o) ((o) ^ (((o) >> 3) & 0x70))

__device__ __forceinline__ void ldsm_x4(uint32_t& r0, uint32_t& r1,
                                        uint32_t& r2, uint32_t& r3, uint32_t a) {
    asm volatile("ldmatrix.sync.aligned.m8n8.x4.shared.b16 {%0,%1,%2,%3}, [%4];"
                 : "=r"(r0), "=r"(r1), "=r"(r2), "=r"(r3) : "r"(a));
}

__device__ __forceinline__ void mma16816(float* d, const uint32_t* a,
                                         uint32_t b0, uint32_t b1) {
    asm volatile(
        "mma.sync.aligned.m16n8k16.row.col.f32.f16.f16.f32 "
        "{%0,%1,%2,%3}, {%4,%5,%6,%7}, {%8,%9}, {%0,%1,%2,%3};"
        : "+f"(d[0]), "+f"(d[1]), "+f"(d[2]), "+f"(d[3])
        : "r"(a[0]), "r"(a[1]), "r"(a[2]), "r"(a[3]), "r"(b0), "r"(b1));
}

// ------------------------------------------------------------------ SMEM layout
// stage: A panel (128 rows x 128B) at +0, W panel (64 rows x 128B) at +16384
static constexpr int W_OFF       = 16384;
static constexpr int STAGE_BYTES = 24576;
static constexpr int SMEM_BYTES  = STAGES * STAGE_BYTES + 1024;  // 74752: 2/SM

// ------------------------------------------------------------------ convert A
__global__ void convert_A_kernel(const float* __restrict__ in) {
    int n4 = (M_DIM * K_DIM) / 4;
    int i = blockIdx.x * blockDim.x + threadIdx.x;
    if (i >= n4) return;
    float4 v = reinterpret_cast<const float4*>(in)[i];
    __half2 h0 = __floats2half2_rn(v.x, v.y);
    __half2 h1 = __floats2half2_rn(v.z, v.w);
    uint2 u;
    u.x = *reinterpret_cast<uint32_t*>(&h0);
    u.y = *reinterpret_cast<uint32_t*>(&h1);
    reinterpret_cast<uint2*>(g_A)[i] = u;
}

// ------------------------------------------------------------------ GEMM pieces
// Bit-trick dequant: q in [0,256) -> fp16 bits (0x6400|q) == 1024+q exactly;
// subtract 1152.0h -> exact (q-128). No I2F.
// Half a W slab: rows [h*32, h*32+32) of the 64-row panel; 2 int4/thread.
__device__ __forceinline__ void dequant_sts_half(const int4* wq, uint32_t w_sm,
                                                 int h, int tid) {
#pragma unroll
    for (int i = 0; i < 2; i++) {
        int li = i * 256 + tid, r = h * 32 + (li >> 4), cg = li & 15;
        uint32_t u0 = hsub2(prmt((uint32_t)wq[i].x, (uint32_t)wq[i].y, 0x5410u)
                                | 0x64006400u, 0x64806480u);
        uint32_t u1 = hsub2(prmt((uint32_t)wq[i].z, (uint32_t)wq[i].w, 0x5410u)
                                | 0x64006400u, 0x64806480u);
        uint32_t dst = w_sm + SWZ(r * 128 + cg * 8);
        asm volatile("st.shared.v2.b32 [%0], {%1, %2};"
                     :: "r"(dst), "r"(u0), "r"(u1) : "memory");
    }
}

// LDG half a W slab into regs (slab sk absolute, half h)
__device__ __forceinline__ void ldg_w_half(int4* wq, const int4* __restrict__ W,
                                           int n0, int sk, int h, int tid) {
    const size_t wrow = (size_t)K_DIM / 4;
#pragma unroll
    for (int i = 0; i < 2; i++) {
        int li = i * 256 + tid, r = h * 32 + (li >> 4), cg = li & 15;
        wq[i] = W[(size_t)(n0 + r) * wrow + sk * (KSLAB / 4) + cg];
    }
}

// issue A-slab cp.async into a stage buffer (absolute k offset); one group
__device__ __forceinline__ void issue_A(const __half* Abase, int kofs,
                                        uint32_t a_sm, int tid) {
#pragma unroll
    for (int i = 0; i < 4; i++) {
        int li = i * 256 + tid, r = li >> 3, c = li & 7;
        const __half* src = Abase + (size_t)r * K_DIM + kofs + c * 8;
        uint32_t dst = a_sm + SWZ(r * 128 + c * 16);
        asm volatile("cp.async.cg.shared.global [%0], [%1], 16;" :: "r"(dst), "l"(src));
    }
    asm volatile("cp.async.commit_group;" ::: "memory");
}

// load one k-step's fragments: A 32x16 (2 ldsm.x4), B 32x16 (2 ldsm.x4)
__device__ __forceinline__ void load_frags(uint32_t a_sm, uint32_t w_sm, int ks,
                                           int lane, int wm, int wn,
                                           uint32_t a[2][4], uint32_t b[4][2]) {
    const int chunk = ks * 2 + (lane >> 4);
#pragma unroll
    for (int mt = 0; mt < 2; mt++) {
        int row = wm * 32 + mt * 16 + (lane & 15);
        ldsm_x4(a[mt][0], a[mt][1], a[mt][2], a[mt][3],
                a_sm + SWZ(row * 128 + chunk * 16));
    }
#pragma unroll
    for (int j = 0; j < 2; j++) {
        int row = wn * 32 + j * 16 + (lane & 15);
        uint32_t t0, t1, t2, t3;
        ldsm_x4(t0, t1, t2, t3, w_sm + SWZ(row * 128 + chunk * 16));
        b[j * 2 + 0][0] = t0;  b[j * 2 + 1][0] = t1;
        b[j * 2 + 0][1] = t2;  b[j * 2 + 1][1] = t3;
    }
}

__global__ void __launch_bounds__(THREADS, 2)
qlinear_hmma_kernel(const int4* __restrict__ W) {
    extern __shared__ char smem_raw[];
    const uint32_t smem = (smem_u32(smem_raw) + 1023u) & ~1023u;

    const int tid  = threadIdx.x;
    const int wid  = tid >> 5;
    const int lane = tid & 31;
    const int wm   = wid >> 1;          // 0..3 : 32-row M strip
    const int wn   = wid & 1;           // 0..1 : 32-col N strip
    const int m0   = blockIdx.x * MTILE;    // m fastest -> weight L2 reuse
    const int n0   = blockIdx.y * NTILE;
    const int kz   = blockIdx.z;            // k-split index
    const int sk0  = kz * NSLABS;           // first slab (units of 64 k)

    const __half* Abase = g_A + (size_t)m0 * K_DIM;

    float acc[2][4][4];
#pragma unroll
    for (int i = 0; i < 2; i++)
#pragma unroll
        for (int j = 0; j < 4; j++)
#pragma unroll
            for (int e = 0; e < 4; e++) acc[i][j][e] = 0.f;

    int4 wq[2];   // half a W slab in flight

    // ---- prologue: stage0 = slab0 complete; stage1 A committed; wq=W(1).h0
    ldg_w_half(wq, W, n0, sk0 + 0, 0, tid);
    issue_A(Abase, (sk0 + 0) * KSLAB, smem, tid);
    issue_A(Abase, (sk0 + 1) * KSLAB, smem + STAGE_BYTES, tid);
    dequant_sts_half(wq, smem + W_OFF, 0, tid);
    ldg_w_half(wq, W, n0, sk0 + 0, 1, tid);
    dequant_sts_half(wq, smem + W_OFF, 1, tid);
    ldg_w_half(wq, W, n0, sk0 + 1, 0, tid);

    // ---- main loop: 3-stage A pipeline; W halves staggered around compute --
#pragma unroll 1
    for (int s = 0; s < NSLABS; s++) {
        const uint32_t a_sm = smem + (s % STAGES) * STAGE_BYTES;
        const uint32_t w_sm = a_sm + W_OFF;
        const uint32_t w_nxt = smem + ((s + 1) % STAGES) * STAGE_BYTES + W_OFF;

        if (s + 2 < NSLABS)
            asm volatile("cp.async.wait_group 1;" ::: "memory");  // A(s) done
        else
            asm volatile("cp.async.wait_group 0;" ::: "memory");
        __syncthreads();   // stage s%3 ready; stage (s+2)%3 free (readers done)

        if (s + 1 < NSLABS) {
            if (s + 2 < NSLABS)
                issue_A(Abase, (sk0 + s + 2) * KSLAB,
                        smem + ((s + 2) % STAGES) * STAGE_BYTES, tid);
            dequant_sts_half(wq, w_nxt, 0, tid);        // W(s+1).h0
            ldg_w_half(wq, W, n0, sk0 + s + 1, 1, tid); // wq = W(s+1).h1
        }

        // compute slab s: 4 k-steps of 16, fragments double-buffered
        uint32_t a[2][2][4], b[2][4][2];
        load_frags(a_sm, w_sm, 0, lane, wm, wn, a[0], b[0]);

        // ks=0 (prefetch ks=1)
        load_frags(a_sm, w_sm, 1, lane, wm, wn, a[1], b[1]);
#pragma unroll
        for (int mt = 0; mt < 2; mt++)
#pragma unroll
            for (int nt = 0; nt < 4; nt++)
                mma16816(acc[mt][nt], a[0][mt], b[0][nt][0], b[0][nt][1]);

        // mid-slab: second W half for s+1, prefetch first half of s+2
        if (s + 1 < NSLABS) {
            dequant_sts_half(wq, w_nxt, 1, tid);        // W(s+1).h1
            if (s + 2 < NSLABS)
                ldg_w_half(wq, W, n0, sk0 + s + 2, 0, tid); // wq = W(s+2).h0
        }

        // ks=1 (prefetch ks=2)
        load_frags(a_sm, w_sm, 2, lane, wm, wn, a[0], b[0]);
#pragma unroll
        for (int mt = 0; mt < 2; mt++)
#pragma unroll
            for (int nt = 0; nt < 4; nt++)
                mma16816(acc[mt][nt], a[1][mt], b[1][nt][0], b[1][nt][1]);

        // ks=2 (prefetch ks=3)
        load_frags(a_sm, w_sm, 3, lane, wm, wn, a[1], b[1]);
#pragma unroll
        for (int mt = 0; mt < 2; mt++)
#pragma unroll
            for (int nt = 0; nt < 4; nt++)
                mma16816(acc[mt][nt], a[0][mt], b[0][nt][0], b[0][nt][1]);

        // ks=3
#pragma unroll
        for (int mt = 0; mt < 2; mt++)
#pragma unroll
            for (int nt = 0; nt < 4; nt++)
                mma16816(acc[mt][nt], a[1][mt], b[1][nt][0], b[1][nt][1]);
    }

    // ---- epilogue: raw partial -> g_P[kz] --------------------------------
    float* Pbase = g_P + (size_t)kz * (M_DIM * N_DIM);
    const int ncb = n0 + wn * 32;
#pragma unroll
    for (int mt = 0; mt < 2; mt++) {
        int row = m0 + wm * 32 + mt * 16 + (lane >> 2);
#pragma unroll
        for (int nt = 0; nt < 4; nt++) {
            int col = ncb + nt * 8 + (lane & 3) * 2;
            float2 v0, v1;
            v0.x = acc[mt][nt][0];  v0.y = acc[mt][nt][1];
            v1.x = acc[mt][nt][2];  v1.y = acc[mt][nt][3];
            *reinterpret_cast<float2*>(Pbase + (size_t)row * N_DIM + col)       = v0;
            *reinterpret_cast<float2*>(Pbase + (size_t)(row + 8) * N_DIM + col) = v1;
        }
    }
}

// ------------------------------------------------------------------ reduction
// out = bias + scale * (p0 + p1), vectorized float4; deterministic order
__global__ void reduce_kernel(const float* __restrict__ scale,
                              const float* __restrict__ bias,
                              float* __restrict__ out) {
    constexpr int N4     = N_DIM / 4;              // 2752
    constexpr int TOTAL4 = (M_DIM * N_DIM) / 4;    // 1409024
    int i = blockIdx.x * blockDim.x + threadIdx.x;
    if (i >= TOTAL4) return;

    const float4* P = reinterpret_cast<const float4*>(g_P);
    float4 s0 = P[i];
    float4 s1 = P[i + TOTAL4];
    float4 s;
    s.x = s0.x + s1.x;
    s.y = s0.y + s1.y;
    s.z = s0.z + s1.z;
    s.w = s0.w + s1.w;

    int nc = i % N4;
    float4 sc = reinterpret_cast<const float4*>(scale)[nc];
    float4 bi = reinterpret_cast<const float4*>(bias)[nc];
    float4 r;
    r.x = fmaf(sc.x, s.x, bi.x);
    r.y = fmaf(sc.y, s.y, bi.y);
    r.z = fmaf(sc.z, s.z, bi.z);
    r.w = fmaf(sc.w, s.w, bi.w);
    reinterpret_cast<float4*>(out)[i] = r;
}

// ------------------------------------------------------------------ launch
extern "C" void kernel_launch(void* const* d_in, const int* in_sizes, int n_in,
                              void* d_out, int out_size) {
    (void)in_sizes; (void)n_in; (void)out_size;
    const float* input = (const float*)d_in[0];
    const int4*  W     = (const int4*)d_in[1];
    const float* scale = (const float*)d_in[2];
    const float* bias  = (const float*)d_in[3];
    float* out = (float*)d_out;

    convert_A_kernel<<<(M_DIM * K_DIM / 4 + 255) / 256, 256>>>(input);

    cudaFuncSetAttribute(qlinear_hmma_kernel,
                         cudaFuncAttributeMaxDynamicSharedMemorySize, SMEM_BYTES);
    dim3 grid(M_DIM / MTILE, N_DIM / NTILE, KSPLIT);   // m fastest: W L2 reuse
    qlinear_hmma_kernel<<<grid, THREADS, SMEM_BYTES>>>(W);

    constexpr int TOTAL4 = (M_DIM * N_DIM) / 4;
    reduce_kernel<<<(TOTAL4 + 255) / 256, 256>>>(scale, bias, out);
}

// round 14
// speedup vs baseline: 1.0201x; 1.0201x over previous
#include <cuda_runtime.h>
#include <cuda_fp16.h>
#include <cstdint>
#include <cstddef>

// Problem dims (fixed by the reference)
static constexpr int M_DIM  = 512;    // B*S
static constexpr int K_DIM  = 4096;   // IN
static constexpr int N_DIM  = 11008;  // OUT
static constexpr int MTILE  = 128;
static constexpr int NTILE  = 64;
static constexpr int KSLAB  = 64;     // K per pipeline slab
static constexpr int KSPLIT = 2;      // K-split (wave balancing)
static constexpr int KUNIT  = K_DIM / KSPLIT;    // 2048 k per CTA
static constexpr int NSLABS = KUNIT / KSLAB;     // 32 slabs per CTA
static constexpr int STAGES = 3;      // cp.async pipeline depth
static constexpr int THREADS = 128;   // 4 warps: 2(m) x 2(n), 64x32 each

// fp16 activations (exact GEMM except one f32->f16 rounding)
__device__ __half g_A[M_DIM * K_DIM];                     // 4 MB
// split-K raw partial accumulators (deterministic reduction, no atomics)
__device__ float  g_P[(size_t)KSPLIT * M_DIM * N_DIM];    // 45 MB

// ------------------------------------------------------------------ helpers
__device__ __forceinline__ uint32_t smem_u32(const void* p) {
    uint32_t r;
    asm("{ .reg .u64 t; cvta.to.shared.u64 t, %1; cvt.u32.u64 %0, t; }"
        : "=r"(r) : "l"(p));
    return r;
}

__device__ __forceinline__ uint32_t prmt(uint32_t a, uint32_t b, uint32_t s) {
    uint32_t r;
    asm("prmt.b32 %0, %1, %2, %3;" : "=r"(r) : "r"(a), "r"(b), "r"(s));
    return r;
}

__device__ __forceinline__ uint32_t hsub2(uint32_t a, uint32_t b) {
    uint32_t r;
    asm("sub.rn.f16x2 %0, %1, %2;" : "=r"(r) : "r"(a), "r"(b));
    return r;
}

// XOR swizzle on 128B rows (16B chunks) -> conflict-free ldmatrix
#define SWZ(o) ((o) ^ (((o) >> 3) & 0x70))

__device__ __forceinline__ void ldsm_x4(uint32_t& r0, uint32_t& r1,
                                        uint32_t& r2, uint32_t& r3, uint32_t a) {
    asm volatile("ldmatrix.sync.aligned.m8n8.x4.shared.b16 {%0,%1,%2,%3}, [%4];"
                 : "=r"(r0), "=r"(r1), "=r"(r2), "=r"(r3) : "r"(a));
}

__device__ __forceinline__ void mma16816(float* d, const uint32_t* a,
                                         uint32_t b0, uint32_t b1) {
    asm volatile(
        "mma.sync.aligned.m16n8k16.row.col.f32.f16.f16.f32 "
        "{%0,%1,%2,%3}, {%4,%5,%6,%7}, {%8,%9}, {%0,%1,%2,%3};"
        : "+f"(d[0]), "+f"(d[1]), "+f"(d[2]), "+f"(d[3])
        : "r"(a[0]), "r"(a[1]), "r"(a[2]), "r"(a[3]), "r"(b0), "r"(b1));
}

// ------------------------------------------------------------------ SMEM layout
// stage: A panel (128 rows x 128B) at +0, W panel (64 rows x 128B) at +16384
static constexpr int W_OFF       = 16384;
static constexpr int STAGE_BYTES = 24576;
static constexpr int SMEM_BYTES  = STAGES * STAGE_BYTES + 1024;  // 74752: 3/SM

// ------------------------------------------------------------------ convert A
__global__ void convert_A_kernel(const float* __restrict__ in) {
    int n4 = (M_DIM * K_DIM) / 4;
    int i = blockIdx.x * blockDim.x + threadIdx.x;
    if (i >= n4) return;
    float4 v = reinterpret_cast<const float4*>(in)[i];
    __half2 h0 = __floats2half2_rn(v.x, v.y);
    __half2 h1 = __floats2half2_rn(v.z, v.w);
    uint2 u;
    u.x = *reinterpret_cast<uint32_t*>(&h0);
    u.y = *reinterpret_cast<uint32_t*>(&h1);
    reinterpret_cast<uint2*>(g_A)[i] = u;
}

// ------------------------------------------------------------------ GEMM pieces
// Bit-trick dequant: q in [0,256) -> fp16 bits (0x6400|q) == 1024+q exactly;
// subtract 1152.0h -> exact (q-128). No I2F.
__device__ __forceinline__ void dequant_sts(const int4* wq, uint32_t w_sm, int tid) {
#pragma unroll
    for (int i = 0; i < 8; i++) {
        int li = i * 128 + tid, r = li >> 4, cg = li & 15;
        uint32_t u0 = hsub2(prmt((uint32_t)wq[i].x, (uint32_t)wq[i].y, 0x5410u)
                                | 0x64006400u, 0x64806480u);
        uint32_t u1 = hsub2(prmt((uint32_t)wq[i].z, (uint32_t)wq[i].w, 0x5410u)
                                | 0x64006400u, 0x64806480u);
        uint32_t dst = w_sm + SWZ(r * 128 + cg * 8);
        asm volatile("st.shared.v2.b32 [%0], {%1, %2};"
                     :: "r"(dst), "r"(u0), "r"(u1) : "memory");
    }
}

// LDG one W slab (64 rows x 64 int32 = 1024 int4) into regs; sk absolute
__device__ __forceinline__ void ldg_w(int4* wq, const int4* __restrict__ W,
                                      int n0, int sk, int tid) {
    const size_t wrow = (size_t)K_DIM / 4;
#pragma unroll
    for (int i = 0; i < 8; i++) {
        int li = i * 128 + tid, r = li >> 4, cg = li & 15;
        wq[i] = W[(size_t)(n0 + r) * wrow + sk * (KSLAB / 4) + cg];
    }
}

// issue A-slab cp.async into a stage buffer (absolute k offset); one group
__device__ __forceinline__ void issue_A(const __half* Abase, int kofs,
                                        uint32_t a_sm, int tid) {
#pragma unroll
    for (int i = 0; i < 8; i++) {
        int li = i * 128 + tid, r = li >> 3, c = li & 7;
        const __half* src = Abase + (size_t)r * K_DIM + kofs + c * 8;
        uint32_t dst = a_sm + SWZ(r * 128 + c * 16);
        asm volatile("cp.async.cg.shared.global [%0], [%1], 16;" :: "r"(dst), "l"(src));
    }
    asm volatile("cp.async.commit_group;" ::: "memory");
}

__global__ void __launch_bounds__(THREADS, 3)
qlinear_hmma_kernel(const int4* __restrict__ W) {
    extern __shared__ char smem_raw[];
    const uint32_t smem = (smem_u32(smem_raw) + 1023u) & ~1023u;

    const int tid  = threadIdx.x;
    const int wid  = tid >> 5;
    const int lane = tid & 31;
    const int wm   = wid >> 1;          // 0..1 : 64-row M strip
    const int wn   = wid & 1;           // 0..1 : 32-col N strip
    const int m0   = blockIdx.x * MTILE;    // m fastest -> weight L2 reuse
    const int n0   = blockIdx.y * NTILE;
    const int kz   = blockIdx.z;            // k-split index
    const int sk0  = kz * NSLABS;           // first slab (units of 64 k)

    const __half* Abase = g_A + (size_t)m0 * K_DIM;

    float acc[4][4][4];   // 64x32 per warp: 4 m-frags x 4 n-frags
#pragma unroll
    for (int i = 0; i < 4; i++)
#pragma unroll
        for (int j = 0; j < 4; j++)
#pragma unroll
            for (int e = 0; e < 4; e++) acc[i][j][e] = 0.f;

    int4 wq[8];   // one W slab in flight

    // ---- prologue: stage0 complete; stage1 A committed; wq=W(1) ----------
    ldg_w(wq, W, n0, sk0 + 0, tid);
    issue_A(Abase, (sk0 + 0) * KSLAB, smem, tid);
    issue_A(Abase, (sk0 + 1) * KSLAB, smem + STAGE_BYTES, tid);
    dequant_sts(wq, smem + W_OFF, tid);
    ldg_w(wq, W, n0, sk0 + 1, tid);

    // ---- main loop: 3-stage A pipeline, W staged one ahead ----------------
#pragma unroll 1
    for (int s = 0; s < NSLABS; s++) {
        const uint32_t a_sm = smem + (s % STAGES) * STAGE_BYTES;
        const uint32_t w_sm = a_sm + W_OFF;

        if (s + 2 < NSLABS)
            asm volatile("cp.async.wait_group 1;" ::: "memory");  // A(s) done
        else
            asm volatile("cp.async.wait_group 0;" ::: "memory");
        __syncthreads();   // stage s%3 ready; stage (s+2)%3 free (readers done)

        if (s + 1 < NSLABS) {
            if (s + 2 < NSLABS)
                issue_A(Abase, (sk0 + s + 2) * KSLAB,
                        smem + ((s + 2) % STAGES) * STAGE_BYTES, tid);
            dequant_sts(wq, smem + ((s + 1) % STAGES) * STAGE_BYTES + W_OFF, tid);
            if (s + 2 < NSLABS)
                ldg_w(wq, W, n0, sk0 + s + 2, tid);
        }

        // compute slab s: 4 k-steps of 16; 6 ldsm -> 16 MMAs per step
#pragma unroll
        for (int ks = 0; ks < 4; ks++) {
            const int chunk = ks * 2 + (lane >> 4);
            uint32_t a[4][4];
#pragma unroll
            for (int mt = 0; mt < 4; mt++) {
                int row = wm * 64 + mt * 16 + (lane & 15);
                ldsm_x4(a[mt][0], a[mt][1], a[mt][2], a[mt][3],
                        a_sm + SWZ(row * 128 + chunk * 16));
            }
            uint32_t b[4][2];
#pragma unroll
            for (int j = 0; j < 2; j++) {
                int row = wn * 32 + j * 16 + (lane & 15);
                uint32_t t0, t1, t2, t3;
                ldsm_x4(t0, t1, t2, t3, w_sm + SWZ(row * 128 + chunk * 16));
                b[j * 2 + 0][0] = t0;  b[j * 2 + 1][0] = t1;
                b[j * 2 + 0][1] = t2;  b[j * 2 + 1][1] = t3;
            }
#pragma unroll
            for (int mt = 0; mt < 4; mt++)
#pragma unroll
                for (int nt = 0; nt < 4; nt++)
                    mma16816(acc[mt][nt], a[mt], b[nt][0], b[nt][1]);
        }
    }

    // ---- epilogue: raw partial -> g_P[kz] --------------------------------
    float* Pbase = g_P + (size_t)kz * (M_DIM * N_DIM);
    const int ncb = n0 + wn * 32;
#pragma unroll
    for (int mt = 0; mt < 4; mt++) {
        int row = m0 + wm * 64 + mt * 16 + (lane >> 2);
#pragma unroll
        for (int nt = 0; nt < 4; nt++) {
            int col = ncb + nt * 8 + (lane & 3) * 2;
            float2 v0, v1;
            v0.x = acc[mt][nt][0];  v0.y = acc[mt][nt][1];
            v1.x = acc[mt][nt][2];  v1.y = acc[mt][nt][3];
            *reinterpret_cast<float2*>(Pbase + (size_t)row * N_DIM + col)       = v0;
            *reinterpret_cast<float2*>(Pbase + (size_t)(row + 8) * N_DIM + col) = v1;
        }
    }
}

// ------------------------------------------------------------------ reduction
// out = bias + scale * (p0 + p1), vectorized float4; deterministic order
__global__ void reduce_kernel(const float* __restrict__ scale,
                              const float* __restrict__ bias,
                              float* __restrict__ out) {
    constexpr int N4     = N_DIM / 4;              // 2752
    constexpr int TOTAL4 = (M_DIM * N_DIM) / 4;    // 1409024
    int i = blockIdx.x * blockDim.x + threadIdx.x;
    if (i >= TOTAL4) return;

    const float4* P = reinterpret_cast<const float4*>(g_P);
    float4 s0 = P[i];
    float4 s1 = P[i + TOTAL4];
    float4 s;
    s.x = s0.x + s1.x;
    s.y = s0.y + s1.y;
    s.z = s0.z + s1.z;
    s.w = s0.w + s1.w;

    int nc = i % N4;
    float4 sc = reinterpret_cast<const float4*>(scale)[nc];
    float4 bi = reinterpret_cast<const float4*>(bias)[nc];
    float4 r;
    r.x = fmaf(sc.x, s.x, bi.x);
    r.y = fmaf(sc.y, s.y, bi.y);
    r.z = fmaf(sc.z, s.z, bi.z);
    r.w = fmaf(sc.w, s.w, bi.w);
    reinterpret_cast<float4*>(out)[i] = r;
}

// ------------------------------------------------------------------ launch
extern "C" void kernel_launch(void* const* d_in, const int* in_sizes, int n_in,
                              void* d_out, int out_size) {
    (void)in_sizes; (void)n_in; (void)out_size;
    const float* input = (const float*)d_in[0];
    const int4*  W     = (const int4*)d_in[1];
    const float* scale = (const float*)d_in[2];
    const float* bias  = (const float*)d_in[3];
    float* out = (float*)d_out;

    convert_A_kernel<<<(M_DIM * K_DIM / 4 + 255) / 256, 256>>>(input);

    cudaFuncSetAttribute(qlinear_hmma_kernel,
                         cudaFuncAttributeMaxDynamicSharedMemorySize, SMEM_BYTES);
    dim3 grid(M_DIM / MTILE, N_DIM / NTILE, KSPLIT);   // m fastest: W L2 reuse
    qlinear_hmma_kernel<<<grid, THREADS, SMEM_BYTES>>>(W);

    constexpr int TOTAL4 = (M_DIM * N_DIM) / 4;
    reduce_kernel<<<(TOTAL4 + 255) / 256, 256>>>(scale, bias, out);
}

// round 15
// speedup vs baseline: 1.0569x; 1.0361x over previous
#include <cuda_runtime.h>
#include <cuda_fp16.h>
#include <cstdint>
#include <cstddef>

// Problem dims (fixed by the reference)
static constexpr int M_DIM  = 512;    // B*S
static constexpr int K_DIM  = 4096;   // IN
static constexpr int N_DIM  = 11008;  // OUT
static constexpr int MTILE  = 128;
static constexpr int NTILE  = 64;     // 2 CTAs/SM
static constexpr int KSLAB  = 64;     // K per pipeline slab
static constexpr int KSPLIT = 2;      // K-split (wave balancing)
static constexpr int KUNIT  = K_DIM / KSPLIT;    // 2048 k per CTA
static constexpr int NSLABS = KUNIT / KSLAB;     // 32 slabs per CTA
static constexpr int STAGES = 4;      // cp.async pipeline depth
static constexpr int THREADS = 256;   // 8 warps: 4(m) x 2(n), 32x32 each
static constexpr int NTILES  = (M_DIM / MTILE) * (N_DIM / NTILE);   // 344

// fp16 activations (exact GEMM except one f32->f16 rounding)
__device__ __half g_A[M_DIM * K_DIM];                     // 4 MB
// split-K raw partial accumulators (deterministic reduction, no atomics on data)
__device__ float  g_P[(size_t)KSPLIT * M_DIM * N_DIM];    // 45 MB
// per-(m,n)-tile arrival counters for fused reduction
__device__ int    g_flag[NTILES];

// ------------------------------------------------------------------ helpers
__device__ __forceinline__ uint32_t smem_u32(const void* p) {
    uint32_t r;
    asm("{ .reg .u64 t; cvta.to.shared.u64 t, %1; cvt.u32.u64 %0, t; }"
        : "=r"(r) : "l"(p));
    return r;
}

__device__ __forceinline__ uint32_t prmt(uint32_t a, uint32_t b, uint32_t s) {
    uint32_t r;
    asm("prmt.b32 %0, %1, %2, %3;" : "=r"(r) : "r"(a), "r"(b), "r"(s));
    return r;
}

__device__ __forceinline__ uint32_t hsub2(uint32_t a, uint32_t b) {
    uint32_t r;
    asm("sub.rn.f16x2 %0, %1, %2;" : "=r"(r) : "r"(a), "r"(b));
    return r;
}

// XOR swizzle on 128B rows (16B chunks) -> conflict-free ldmatrix
#define SWZ(o) ((o) ^ (((o) >> 3) & 0x70))

__device__ __forceinline__ void ldsm_x4(uint32_t& r0, uint32_t& r1,
                                        uint32_t& r2, uint32_t& r3, uint32_t a) {
    asm volatile("ldmatrix.sync.aligned.m8n8.x4.shared.b16 {%0,%1,%2,%3}, [%4];"
                 : "=r"(r0), "=r"(r1), "=r"(r2), "=r"(r3) : "r"(a));
}

__device__ __forceinline__ void mma16816(float* d, const uint32_t* a,
                                         uint32_t b0, uint32_t b1) {
    asm volatile(
        "mma.sync.aligned.m16n8k16.row.col.f32.f16.f16.f32 "
        "{%0,%1,%2,%3}, {%4,%5,%6,%7}, {%8,%9}, {%0,%1,%2,%3};"
        : "+f"(d[0]), "+f"(d[1]), "+f"(d[2]), "+f"(d[3])
        : "r"(a[0]), "r"(a[1]), "r"(a[2]), "r"(a[3]), "r"(b0), "r"(b1));
}

// ------------------------------------------------------------------ SMEM layout
// stage: A panel (128 rows x 128B) at +0, W panel (64 rows x 128B) at +16384
static constexpr int W_OFF       = 16384;
static constexpr int STAGE_BYTES = 24576;
static constexpr int SMEM_BYTES  = STAGES * STAGE_BYTES + 1024;  // 99328: 2/SM

// ------------------------------------------------------------------ small kernels
__global__ void convert_A_kernel(const float* __restrict__ in) {
    constexpr int N4 = (M_DIM * K_DIM) / 4;          // 524288
    const int stride = gridDim.x * blockDim.x;       // 262144
    int i = blockIdx.x * blockDim.x + threadIdx.x;
    // two independent elements in flight per thread (MLP)
    float4 v0 = reinterpret_cast<const float4*>(in)[i];
    float4 v1 = reinterpret_cast<const float4*>(in)[i + stride];
    (void)N4;
    uint2 u0, u1;
    {
        __half2 h0 = __floats2half2_rn(v0.x, v0.y);
        __half2 h1 = __floats2half2_rn(v0.z, v0.w);
        u0.x = *reinterpret_cast<uint32_t*>(&h0);
        u0.y = *reinterpret_cast<uint32_t*>(&h1);
    }
    {
        __half2 h0 = __floats2half2_rn(v1.x, v1.y);
        __half2 h1 = __floats2half2_rn(v1.z, v1.w);
        u1.x = *reinterpret_cast<uint32_t*>(&h0);
        u1.y = *reinterpret_cast<uint32_t*>(&h1);
    }
    reinterpret_cast<uint2*>(g_A)[i]          = u0;
    reinterpret_cast<uint2*>(g_A)[i + stride] = u1;
}

__global__ void init_flags_kernel() {
    int i = blockIdx.x * blockDim.x + threadIdx.x;
    if (i < NTILES) g_flag[i] = 0;
}

// ------------------------------------------------------------------ GEMM pieces
// Bit-trick dequant: q in [0,256) -> fp16 bits (0x6400|q) == 1024+q exactly;
// subtract 1152.0h -> exact (q-128). No I2F.
__device__ __forceinline__ void dequant_sts(const int4* wq, uint32_t w_sm, int tid) {
#pragma unroll
    for (int i = 0; i < 4; i++) {
        int li = i * 256 + tid, r = li >> 4, cg = li & 15;
        uint32_t u0 = hsub2(prmt((uint32_t)wq[i].x, (uint32_t)wq[i].y, 0x5410u)
                                | 0x64006400u, 0x64806480u);
        uint32_t u1 = hsub2(prmt((uint32_t)wq[i].z, (uint32_t)wq[i].w, 0x5410u)
                                | 0x64006400u, 0x64806480u);
        uint32_t dst = w_sm + SWZ(r * 128 + cg * 8);
        asm volatile("st.shared.v2.b32 [%0], {%1, %2};"
                     :: "r"(dst), "r"(u0), "r"(u1) : "memory");
    }
}

// LDG one W slab into regs (slab index sk in units of 64 k, absolute)
__device__ __forceinline__ void ldg_w(int4* wq, const int4* __restrict__ W,
                                      int n0, int sk, int tid) {
    const size_t wrow = (size_t)K_DIM / 4;
#pragma unroll
    for (int i = 0; i < 4; i++) {
        int li = i * 256 + tid, r = li >> 4, cg = li & 15;
        wq[i] = W[(size_t)(n0 + r) * wrow + sk * (KSLAB / 4) + cg];
    }
}

// issue A-slab cp.async into a stage buffer (absolute k offset); one group
__device__ __forceinline__ void issue_A(const __half* Abase, int kofs,
                                        uint32_t a_sm, int tid) {
#pragma unroll
    for (int i = 0; i < 4; i++) {
        int li = i * 256 + tid, r = li >> 3, c = li & 7;
        const __half* src = Abase + (size_t)r * K_DIM + kofs + c * 8;
        uint32_t dst = a_sm + SWZ(r * 128 + c * 16);
        asm volatile("cp.async.cg.shared.global [%0], [%1], 16;" :: "r"(dst), "l"(src));
    }
    asm volatile("cp.async.commit_group;" ::: "memory");
}

__global__ void __launch_bounds__(THREADS, 2)
qlinear_hmma_kernel(const int4* __restrict__ W, const float* __restrict__ scale,
                    const float* __restrict__ bias, float* __restrict__ out) {
    extern __shared__ char smem_raw[];
    const uint32_t smem = (smem_u32(smem_raw) + 1023u) & ~1023u;
    __shared__ int s_last;

    const int tid  = threadIdx.x;
    const int wid  = tid >> 5;
    const int lane = tid & 31;
    const int wm   = wid >> 1;          // 0..3 : 32-row M strip
    const int wn   = wid & 1;           // 0..1 : 32-col N strip
    const int m0   = blockIdx.x * MTILE;    // m fastest -> weight L2 reuse
    const int n0   = blockIdx.y * NTILE;
    const int kz   = blockIdx.z;            // k-split index
    const int sk0  = kz * NSLABS;           // first slab (units of 64 k)

    const __half* Abase = g_A + (size_t)m0 * K_DIM;

    float acc[2][4][4];
#pragma unroll
    for (int i = 0; i < 2; i++)
#pragma unroll
        for (int j = 0; j < 4; j++)
#pragma unroll
            for (int e = 0; e < 4; e++) acc[i][j][e] = 0.f;

    int4 wq[4];   // one W slab in flight

    // ---- prologue: A(0..2) committed; W(0) STS'd; wq=W(1) ----------------
    ldg_w(wq, W, n0, sk0 + 0, tid);
    issue_A(Abase, (sk0 + 0) * KSLAB, smem, tid);
    issue_A(Abase, (sk0 + 1) * KSLAB, smem + 1 * STAGE_BYTES, tid);
    issue_A(Abase, (sk0 + 2) * KSLAB, smem + 2 * STAGE_BYTES, tid);
    dequant_sts(wq, smem + W_OFF, tid);
    ldg_w(wq, W, n0, sk0 + 1, tid);

    // ---- main loop: 4-stage A pipeline, W staged one ahead ----------------
#pragma unroll 1
    for (int s = 0; s < NSLABS; s++) {
        const uint32_t a_sm = smem + (s % STAGES) * STAGE_BYTES;
        const uint32_t w_sm = a_sm + W_OFF;

        if (s <= NSLABS - 3)
            asm volatile("cp.async.wait_group 2;" ::: "memory");  // A(s) done
        else if (s == NSLABS - 2)
            asm volatile("cp.async.wait_group 1;" ::: "memory");
        else
            asm volatile("cp.async.wait_group 0;" ::: "memory");
        __syncthreads();   // stage s%4 ready; stage (s+3)%4 free (readers done)

        if (s + 1 < NSLABS) {
            if (s + 3 < NSLABS)
                issue_A(Abase, (sk0 + s + 3) * KSLAB,
                        smem + ((s + 3) % STAGES) * STAGE_BYTES, tid);
            dequant_sts(wq, smem + ((s + 1) % STAGES) * STAGE_BYTES + W_OFF, tid);
            if (s + 2 < NSLABS)
                ldg_w(wq, W, n0, sk0 + s + 2, tid);
        }

        // compute slab s: 4 k-steps of 16
#pragma unroll
        for (int ks = 0; ks < 4; ks++) {
            const int chunk = ks * 2 + (lane >> 4);
            uint32_t a[2][4];
#pragma unroll
            for (int mt = 0; mt < 2; mt++) {
                int row = wm * 32 + mt * 16 + (lane & 15);
                ldsm_x4(a[mt][0], a[mt][1], a[mt][2], a[mt][3],
                        a_sm + SWZ(row * 128 + chunk * 16));
            }
            uint32_t b[4][2];
#pragma unroll
            for (int j = 0; j < 2; j++) {
                int row = wn * 32 + j * 16 + (lane & 15);
                uint32_t t0, t1, t2, t3;
                ldsm_x4(t0, t1, t2, t3, w_sm + SWZ(row * 128 + chunk * 16));
                b[j * 2 + 0][0] = t0;  b[j * 2 + 1][0] = t1;
                b[j * 2 + 0][1] = t2;  b[j * 2 + 1][1] = t3;
            }
#pragma unroll
            for (int mt = 0; mt < 2; mt++)
#pragma unroll
                for (int nt = 0; nt < 4; nt++)
                    mma16816(acc[mt][nt], a[mt], b[nt][0], b[nt][1]);
        }
    }

    // ---- epilogue 1: store my raw partial (release) ----------------------
    float* Pmine = g_P + (size_t)kz * (M_DIM * N_DIM);
    const int ncb = n0 + wn * 32;
#pragma unroll
    for (int mt = 0; mt < 2; mt++) {
        int row = m0 + wm * 32 + mt * 16 + (lane >> 2);
#pragma unroll
        for (int nt = 0; nt < 4; nt++) {
            int col = ncb + nt * 8 + (lane & 3) * 2;
            float2 v0, v1;
            v0.x = acc[mt][nt][0];  v0.y = acc[mt][nt][1];
            v1.x = acc[mt][nt][2];  v1.y = acc[mt][nt][3];
            *reinterpret_cast<float2*>(Pmine + (size_t)row * N_DIM + col)       = v0;
            *reinterpret_cast<float2*>(Pmine + (size_t)(row + 8) * N_DIM + col) = v1;
        }
    }
    __threadfence();
    if (tid == 0)
        s_last = atomicAdd(&g_flag[blockIdx.y * (M_DIM / MTILE) + blockIdx.x], 1);
    __syncthreads();

    // ---- epilogue 2: last arriver fuses the reduction --------------------
    if (s_last == 1) {
        __threadfence();   // acquire: partner's partial now visible
        const float* Pother = g_P + (size_t)(kz ^ 1) * (M_DIM * N_DIM);
#pragma unroll
        for (int mt = 0; mt < 2; mt++) {
            int row = m0 + wm * 32 + mt * 16 + (lane >> 2);
#pragma unroll
            for (int nt = 0; nt < 4; nt++) {
                int col = ncb + nt * 8 + (lane & 3) * 2;
                float sc0 = __ldg(&scale[col]),     sc1 = __ldg(&scale[col + 1]);
                float bi0 = __ldg(&bias[col]),      bi1 = __ldg(&bias[col + 1]);
                float2 o0 = *reinterpret_cast<const float2*>(
                                Pother + (size_t)row * N_DIM + col);
                float2 o1 = *reinterpret_cast<const float2*>(
                                Pother + (size_t)(row + 8) * N_DIM + col);
                float2 r0, r1;
                r0.x = fmaf(sc0, acc[mt][nt][0] + o0.x, bi0);
                r0.y = fmaf(sc1, acc[mt][nt][1] + o0.y, bi1);
                r1.x = fmaf(sc0, acc[mt][nt][2] + o1.x, bi0);
                r1.y = fmaf(sc1, acc[mt][nt][3] + o1.y, bi1);
                *reinterpret_cast<float2*>(out + (size_t)row * N_DIM + col)       = r0;
                *reinterpret_cast<float2*>(out + (size_t)(row + 8) * N_DIM + col) = r1;
            }
        }
    }
}

// ------------------------------------------------------------------ launch
extern "C" void kernel_launch(void* const* d_in, const int* in_sizes, int n_in,
                              void* d_out, int out_size) {
    (void)in_sizes; (void)n_in; (void)out_size;
    const float* input = (const float*)d_in[0];
    const int4*  W     = (const int4*)d_in[1];
    const float* scale = (const float*)d_in[2];
    const float* bias  = (const float*)d_in[3];
    float* out = (float*)d_out;

    init_flags_kernel<<<(NTILES + 255) / 256, 256>>>();
    convert_A_kernel<<<1024, 256>>>(input);   // 2 float4 per thread

    cudaFuncSetAttribute(qlinear_hmma_kernel,
                         cudaFuncAttributeMaxDynamicSharedMemorySize, SMEM_BYTES);
    dim3 grid(M_DIM / MTILE, N_DIM / NTILE, KSPLIT);   // m fastest: W L2 reuse
    qlinear_hmma_kernel<<<grid, THREADS, SMEM_BYTES>>>(W, scale, bias, out);
}

// round 16
// speedup vs baseline: 1.0841x; 1.0257x over previous
#include <cuda_runtime.h>
#include <cuda_fp16.h>
#include <cstdint>
#include <cstddef>

// Problem dims (fixed by the reference)
static constexpr int M_DIM  = 512;    // B*S
static constexpr int K_DIM  = 4096;   // IN
static constexpr int N_DIM  = 11008;  // OUT
static constexpr int MTILE  = 128;
static constexpr int NTILE  = 64;     // 2 CTAs/SM
static constexpr int KSLAB  = 64;     // K per pipeline slab
static constexpr int KSPLIT = 2;      // K-split (wave balancing)
static constexpr int KUNIT  = K_DIM / KSPLIT;    // 2048 k per CTA
static constexpr int NSLABS = KUNIT / KSLAB;     // 32 slabs per CTA
static constexpr int STAGES = 3;      // cp.async pipeline depth
static constexpr int THREADS = 256;   // 8 warps: 4(m) x 2(n), 32x32 each
static constexpr int NTILES  = (M_DIM / MTILE) * (N_DIM / NTILE);   // 688 tiles

// fp16 activations (exact GEMM except one f32->f16 rounding)
__device__ __half g_A[M_DIM * K_DIM];                     // 4 MB
// split-K raw partial accumulators (deterministic reduction, no atomics on data)
__device__ float  g_P[(size_t)KSPLIT * M_DIM * N_DIM];    // 45 MB
// per-(m,n)-tile arrival counters for fused reduction
__device__ int    g_flag[NTILES];

// ------------------------------------------------------------------ helpers
__device__ __forceinline__ uint32_t smem_u32(const void* p) {
    uint32_t r;
    asm("{ .reg .u64 t; cvta.to.shared.u64 t, %1; cvt.u32.u64 %0, t; }"
        : "=r"(r) : "l"(p));
    return r;
}

__device__ __forceinline__ uint32_t prmt(uint32_t a, uint32_t b, uint32_t s) {
    uint32_t r;
    asm("prmt.b32 %0, %1, %2, %3;" : "=r"(r) : "r"(a), "r"(b), "r"(s));
    return r;
}

__device__ __forceinline__ uint32_t hsub2(uint32_t a, uint32_t b) {
    uint32_t r;
    asm("sub.rn.f16x2 %0, %1, %2;" : "=r"(r) : "r"(a), "r"(b));
    return r;
}

// XOR swizzle on 128B rows (16B chunks) -> conflict-free ldmatrix
#define SWZ(o) ((o) ^ (((o) >> 3) & 0x70))

__device__ __forceinline__ void ldsm_x4(uint32_t& r0, uint32_t& r1,
                                        uint32_t& r2, uint32_t& r3, uint32_t a) {
    asm volatile("ldmatrix.sync.aligned.m8n8.x4.shared.b16 {%0,%1,%2,%3}, [%4];"
                 : "=r"(r0), "=r"(r1), "=r"(r2), "=r"(r3) : "r"(a));
}

__device__ __forceinline__ void mma16816(float* d, const uint32_t* a,
                                         uint32_t b0, uint32_t b1) {
    asm volatile(
        "mma.sync.aligned.m16n8k16.row.col.f32.f16.f16.f32 "
        "{%0,%1,%2,%3}, {%4,%5,%6,%7}, {%8,%9}, {%0,%1,%2,%3};"
        : "+f"(d[0]), "+f"(d[1]), "+f"(d[2]), "+f"(d[3])
        : "r"(a[0]), "r"(a[1]), "r"(a[2]), "r"(a[3]), "r"(b0), "r"(b1));
}

// ------------------------------------------------------------------ SMEM layout
// stage: A panel (128 rows x 128B) at +0, W panel (64 rows x 128B) at +16384
static constexpr int W_OFF       = 16384;
static constexpr int STAGE_BYTES = 24576;
static constexpr int SMEM_BYTES  = STAGES * STAGE_BYTES + 1024;  // 74752: 2/SM

// ------------------------------------------------------------------ convert A (+ flag init)
__global__ void convert_A_kernel(const float* __restrict__ in) {
    int n4 = (M_DIM * K_DIM) / 4;
    int i = blockIdx.x * blockDim.x + threadIdx.x;
    // fold flag zeroing into this kernel (no extra launch)
    if (blockIdx.x == 0) {
        for (int f = threadIdx.x; f < NTILES; f += blockDim.x) g_flag[f] = 0;
    }
    if (i >= n4) return;
    float4 v = reinterpret_cast<const float4*>(in)[i];
    __half2 h0 = __floats2half2_rn(v.x, v.y);
    __half2 h1 = __floats2half2_rn(v.z, v.w);
    uint2 u;
    u.x = *reinterpret_cast<uint32_t*>(&h0);
    u.y = *reinterpret_cast<uint32_t*>(&h1);
    reinterpret_cast<uint2*>(g_A)[i] = u;
}

// ------------------------------------------------------------------ GEMM pieces
// Bit-trick dequant: q in [0,256) -> fp16 bits (0x6400|q) == 1024+q exactly;
// subtract 1152.0h -> exact (q-128). No I2F.
__device__ __forceinline__ void dequant_sts(const int4* wq, uint32_t w_sm, int tid) {
#pragma unroll
    for (int i = 0; i < 4; i++) {
        int li = i * 256 + tid, r = li >> 4, cg = li & 15;
        uint32_t u0 = hsub2(prmt((uint32_t)wq[i].x, (uint32_t)wq[i].y, 0x5410u)
                                | 0x64006400u, 0x64806480u);
        uint32_t u1 = hsub2(prmt((uint32_t)wq[i].z, (uint32_t)wq[i].w, 0x5410u)
                                | 0x64006400u, 0x64806480u);
        uint32_t dst = w_sm + SWZ(r * 128 + cg * 8);
        asm volatile("st.shared.v2.b32 [%0], {%1, %2};"
                     :: "r"(dst), "r"(u0), "r"(u1) : "memory");
    }
}

// LDG one W slab into regs (slab index sk in units of 64 k, absolute)
__device__ __forceinline__ void ldg_w(int4* wq, const int4* __restrict__ W,
                                      int n0, int sk, int tid) {
    const size_t wrow = (size_t)K_DIM / 4;
#pragma unroll
    for (int i = 0; i < 4; i++) {
        int li = i * 256 + tid, r = li >> 4, cg = li & 15;
        wq[i] = W[(size_t)(n0 + r) * wrow + sk * (KSLAB / 4) + cg];
    }
}

// issue A-slab cp.async into a stage buffer (absolute k offset); one group
__device__ __forceinline__ void issue_A(const __half* Abase, int kofs,
                                        uint32_t a_sm, int tid) {
#pragma unroll
    for (int i = 0; i < 4; i++) {
        int li = i * 256 + tid, r = li >> 3, c = li & 7;
        const __half* src = Abase + (size_t)r * K_DIM + kofs + c * 8;
        uint32_t dst = a_sm + SWZ(r * 128 + c * 16);
        asm volatile("cp.async.cg.shared.global [%0], [%1], 16;" :: "r"(dst), "l"(src));
    }
    asm volatile("cp.async.commit_group;" ::: "memory");
}

__global__ void __launch_bounds__(THREADS, 2)
qlinear_hmma_kernel(const int4* __restrict__ W, const float* __restrict__ scale,
                    const float* __restrict__ bias, float* __restrict__ out) {
    extern __shared__ char smem_raw[];
    const uint32_t smem = (smem_u32(smem_raw) + 1023u) & ~1023u;
    __shared__ int s_last;

    const int tid  = threadIdx.x;
    const int wid  = tid >> 5;
    const int lane = tid & 31;
    const int wm   = wid >> 1;          // 0..3 : 32-row M strip
    const int wn   = wid & 1;           // 0..1 : 32-col N strip
    const int m0   = blockIdx.x * MTILE;    // m fastest -> weight L2 reuse
    const int n0   = blockIdx.y * NTILE;
    const int kz   = blockIdx.z;            // k-split index
    const int sk0  = kz * NSLABS;           // first slab (units of 64 k)

    const __half* Abase = g_A + (size_t)m0 * K_DIM;

    float acc[2][4][4];
#pragma unroll
    for (int i = 0; i < 2; i++)
#pragma unroll
        for (int j = 0; j < 4; j++)
#pragma unroll
            for (int e = 0; e < 4; e++) acc[i][j][e] = 0.f;

    int4 wq[4];   // one W slab in flight

    // ---- prologue: A(0),A(1) committed; W(0) STS'd; wq=W(1) --------------
    ldg_w(wq, W, n0, sk0 + 0, tid);
    issue_A(Abase, (sk0 + 0) * KSLAB, smem, tid);
    issue_A(Abase, (sk0 + 1) * KSLAB, smem + STAGE_BYTES, tid);
    dequant_sts(wq, smem + W_OFF, tid);
    ldg_w(wq, W, n0, sk0 + 1, tid);

    // ---- main loop: 3-stage A pipeline, W staged one ahead ----------------
#pragma unroll 1
    for (int s = 0; s < NSLABS; s++) {
        const uint32_t a_sm = smem + (s % STAGES) * STAGE_BYTES;
        const uint32_t w_sm = a_sm + W_OFF;

        if (s + 2 < NSLABS)
            asm volatile("cp.async.wait_group 1;" ::: "memory");  // A(s) done
        else
            asm volatile("cp.async.wait_group 0;" ::: "memory");
        __syncthreads();   // stage s%3 ready; stage (s+2)%3 free (readers done)

        if (s + 1 < NSLABS) {
            if (s + 2 < NSLABS)
                issue_A(Abase, (sk0 + s + 2) * KSLAB,
                        smem + ((s + 2) % STAGES) * STAGE_BYTES, tid);
            dequant_sts(wq, smem + ((s + 1) % STAGES) * STAGE_BYTES + W_OFF, tid);
            if (s + 2 < NSLABS)
                ldg_w(wq, W, n0, sk0 + s + 2, tid);
        }

        // compute slab s: 4 k-steps of 16
#pragma unroll
        for (int ks = 0; ks < 4; ks++) {
            const int chunk = ks * 2 + (lane >> 4);
            uint32_t a[2][4];
#pragma unroll
            for (int mt = 0; mt < 2; mt++) {
                int row = wm * 32 + mt * 16 + (lane & 15);
                ldsm_x4(a[mt][0], a[mt][1], a[mt][2], a[mt][3],
                        a_sm + SWZ(row * 128 + chunk * 16));
            }
            uint32_t b[4][2];
#pragma unroll
            for (int j = 0; j < 2; j++) {
                int row = wn * 32 + j * 16 + (lane & 15);
                uint32_t t0, t1, t2, t3;
                ldsm_x4(t0, t1, t2, t3, w_sm + SWZ(row * 128 + chunk * 16));
                b[j * 2 + 0][0] = t0;  b[j * 2 + 1][0] = t1;
                b[j * 2 + 0][1] = t2;  b[j * 2 + 1][1] = t3;
            }
#pragma unroll
            for (int mt = 0; mt < 2; mt++)
#pragma unroll
                for (int nt = 0; nt < 4; nt++)
                    mma16816(acc[mt][nt], a[mt], b[nt][0], b[nt][1]);
        }
    }

    // ---- epilogue 1: store my raw partial (release), acc dies here -------
    float* Pmine = g_P + (size_t)kz * (M_DIM * N_DIM);
    const int ncb = n0 + wn * 32;
#pragma unroll
    for (int mt = 0; mt < 2; mt++) {
        int row = m0 + wm * 32 + mt * 16 + (lane >> 2);
#pragma unroll
        for (int nt = 0; nt < 4; nt++) {
            int col = ncb + nt * 8 + (lane & 3) * 2;
            float2 v0, v1;
            v0.x = acc[mt][nt][0];  v0.y = acc[mt][nt][1];
            v1.x = acc[mt][nt][2];  v1.y = acc[mt][nt][3];
            *reinterpret_cast<float2*>(Pmine + (size_t)row * N_DIM + col)       = v0;
            *reinterpret_cast<float2*>(Pmine + (size_t)(row + 8) * N_DIM + col) = v1;
        }
    }
    __threadfence();
    if (tid == 0)
        s_last = atomicAdd(&g_flag[blockIdx.y * (M_DIM / MTILE) + blockIdx.x], 1);
    __syncthreads();

    // ---- epilogue 2: last arriver reduces from g_P (acc-free; fixed order:
    //      always P0 + P1 -> bitwise deterministic either arrival order) ----
    if (s_last == 1) {
        __threadfence();   // acquire: partner's partial visible
        const float* P0 = g_P;
        const float* P1 = g_P + (size_t)(M_DIM * N_DIM);
        // 128x64 tile, 256 threads, float4 lanes: 16 cols (4 float4) x 128 rows
        const int c4   = (tid & 3) * 4;              // float4 col within tile
        const int rstp = 64;                          // rows per pass of 256 thr
#pragma unroll
        for (int rr = 0; rr < 2; rr++) {
            int row = m0 + (tid >> 2) + rr * rstp;
            size_t base = (size_t)row * N_DIM + n0;
#pragma unroll
            for (int cc = 0; cc < 4; cc++) {
                int col = cc * 16 + c4;
                float4 p0 = *reinterpret_cast<const float4*>(P0 + base + col);
                float4 p1 = *reinterpret_cast<const float4*>(P1 + base + col);
                float4 sc = *reinterpret_cast<const float4*>(scale + n0 + col);
                float4 bi = *reinterpret_cast<const float4*>(bias + n0 + col);
                float4 r;
                r.x = fmaf(sc.x, p0.x + p1.x, bi.x);
                r.y = fmaf(sc.y, p0.y + p1.y, bi.y);
                r.z = fmaf(sc.z, p0.z + p1.z, bi.z);
                r.w = fmaf(sc.w, p0.w + p1.w, bi.w);
                *reinterpret_cast<float4*>(out + base + col) = r;
            }
        }
    }
}

// ------------------------------------------------------------------ launch
extern "C" void kernel_launch(void* const* d_in, const int* in_sizes, int n_in,
                              void* d_out, int out_size) {
    (void)in_sizes; (void)n_in; (void)out_size;
    const float* input = (const float*)d_in[0];
    const int4*  W     = (const int4*)d_in[1];
    const float* scale = (const float*)d_in[2];
    const float* bias  = (const float*)d_in[3];
    float* out = (float*)d_out;

    convert_A_kernel<<<(M_DIM * K_DIM / 4 + 255) / 256, 256>>>(input);

    cudaFuncSetAttribute(qlinear_hmma_kernel,
                         cudaFuncAttributeMaxDynamicSharedMemorySize, SMEM_BYTES);
    dim3 grid(M_DIM / MTILE, N_DIM / NTILE, KSPLIT);   // m fastest: W L2 reuse
    qlinear_hmma_kernel<<<grid, THREADS, SMEM_BYTES>>>(W, scale, bias, out);
}

// round 17
// speedup vs baseline: 1.1488x; 1.0597x over previous
#include <cuda_runtime.h>
#include <cuda_fp16.h>
#include <cstdint>
#include <cstddef>

// Problem dims (fixed by the reference)
static constexpr int M_DIM  = 512;    // B*S
static constexpr int K_DIM  = 4096;   // IN
static constexpr int N_DIM  = 11008;  // OUT
static constexpr int MTILE  = 128;
static constexpr int NTILE  = 64;     // 2 CTAs/SM
static constexpr int KSLAB  = 64;     // K per pipeline slab (64 total slabs)
static constexpr int KSPLIT = 3;      // 2064 CTAs = 6.97 waves on 296 slots
static constexpr int STAGES = 3;      // cp.async pipeline depth
static constexpr int THREADS = 256;   // 8 warps: 4(m) x 2(n), 32x32 each

// fp16 activations (exact GEMM except one f32->f16 rounding)
__device__ __half g_A[M_DIM * K_DIM];                     // 4 MB
// split-K raw partial accumulators (deterministic reduction, no atomics)
__device__ float  g_P[(size_t)KSPLIT * M_DIM * N_DIM];    // 67.5 MB

// ------------------------------------------------------------------ helpers
__device__ __forceinline__ uint32_t smem_u32(const void* p) {
    uint32_t r;
    asm("{ .reg .u64 t; cvta.to.shared.u64 t, %1; cvt.u32.u64 %0, t; }"
        : "=r"(r) : "l"(p));
    return r;
}

__device__ __forceinline__ uint32_t prmt(uint32_t a, uint32_t b, uint32_t s) {
    uint32_t r;
    asm("prmt.b32 %0, %1, %2, %3;" : "=r"(r) : "r"(a), "r"(b), "r"(s));
    return r;
}

__device__ __forceinline__ uint32_t hsub2(uint32_t a, uint32_t b) {
    uint32_t r;
    asm("sub.rn.f16x2 %0, %1, %2;" : "=r"(r) : "r"(a), "r"(b));
    return r;
}

// XOR swizzle on 128B rows (16B chunks) -> conflict-free ldmatrix
#define SWZ(o) ((o) ^ (((o) >> 3) & 0x70))

__device__ __forceinline__ void ldsm_x4(uint32_t& r0, uint32_t& r1,
                                        uint32_t& r2, uint32_t& r3, uint32_t a) {
    asm volatile("ldmatrix.sync.aligned.m8n8.x4.shared.b16 {%0,%1,%2,%3}, [%4];"
                 : "=r"(r0), "=r"(r1), "=r"(r2), "=r"(r3) : "r"(a));
}

__device__ __forceinline__ void mma16816(float* d, const uint32_t* a,
                                         uint32_t b0, uint32_t b1) {
    asm volatile(
        "mma.sync.aligned.m16n8k16.row.col.f32.f16.f16.f32 "
        "{%0,%1,%2,%3}, {%4,%5,%6,%7}, {%8,%9}, {%0,%1,%2,%3};"
        : "+f"(d[0]), "+f"(d[1]), "+f"(d[2]), "+f"(d[3])
        : "r"(a[0]), "r"(a[1]), "r"(a[2]), "r"(a[3]), "r"(b0), "r"(b1));
}

// ------------------------------------------------------------------ SMEM layout
// stage: A panel (128 rows x 128B) at +0, W panel (64 rows x 128B) at +16384
static constexpr int W_OFF       = 16384;
static constexpr int STAGE_BYTES = 24576;
static constexpr int SMEM_BYTES  = STAGES * STAGE_BYTES + 1024;  // 74752: 2/SM

// ------------------------------------------------------------------ convert A
__global__ void convert_A_kernel(const float* __restrict__ in) {
    int n4 = (M_DIM * K_DIM) / 4;
    int i = blockIdx.x * blockDim.x + threadIdx.x;
    if (i >= n4) return;
    float4 v = reinterpret_cast<const float4*>(in)[i];
    __half2 h0 = __floats2half2_rn(v.x, v.y);
    __half2 h1 = __floats2half2_rn(v.z, v.w);
    uint2 u;
    u.x = *reinterpret_cast<uint32_t*>(&h0);
    u.y = *reinterpret_cast<uint32_t*>(&h1);
    reinterpret_cast<uint2*>(g_A)[i] = u;
}

// ------------------------------------------------------------------ GEMM pieces
// Bit-trick dequant: q in [0,256) -> fp16 bits (0x6400|q) == 1024+q exactly;
// subtract 1152.0h -> exact (q-128). No I2F.
__device__ __forceinline__ void dequant_sts(const int4* wq, uint32_t w_sm, int tid) {
#pragma unroll
    for (int i = 0; i < 4; i++) {
        int li = i * 256 + tid, r = li >> 4, cg = li & 15;
        uint32_t u0 = hsub2(prmt((uint32_t)wq[i].x, (uint32_t)wq[i].y, 0x5410u)
                                | 0x64006400u, 0x64806480u);
        uint32_t u1 = hsub2(prmt((uint32_t)wq[i].z, (uint32_t)wq[i].w, 0x5410u)
                                | 0x64006400u, 0x64806480u);
        uint32_t dst = w_sm + SWZ(r * 128 + cg * 8);
        asm volatile("st.shared.v2.b32 [%0], {%1, %2};"
                     :: "r"(dst), "r"(u0), "r"(u1) : "memory");
    }
}

// LDG one W slab into regs (slab index sk in units of 64 k, absolute)
__device__ __forceinline__ void ldg_w(int4* wq, const int4* __restrict__ W,
                                      int n0, int sk, int tid) {
    const size_t wrow = (size_t)K_DIM / 4;
#pragma unroll
    for (int i = 0; i < 4; i++) {
        int li = i * 256 + tid, r = li >> 4, cg = li & 15;
        wq[i] = W[(size_t)(n0 + r) * wrow + sk * (KSLAB / 4) + cg];
    }
}

// issue A-slab cp.async into a stage buffer (absolute k offset); one group
__device__ __forceinline__ void issue_A(const __half* Abase, int kofs,
                                        uint32_t a_sm, int tid) {
#pragma unroll
    for (int i = 0; i < 4; i++) {
        int li = i * 256 + tid, r = li >> 3, c = li & 7;
        const __half* src = Abase + (size_t)r * K_DIM + kofs + c * 8;
        uint32_t dst = a_sm + SWZ(r * 128 + c * 16);
        asm volatile("cp.async.cg.shared.global [%0], [%1], 16;" :: "r"(dst), "l"(src));
    }
    asm volatile("cp.async.commit_group;" ::: "memory");
}

__global__ void __launch_bounds__(THREADS, 2)
qlinear_hmma_kernel(const int4* __restrict__ W) {
    extern __shared__ char smem_raw[];
    const uint32_t smem = (smem_u32(smem_raw) + 1023u) & ~1023u;

    const int tid  = threadIdx.x;
    const int wid  = tid >> 5;
    const int lane = tid & 31;
    const int wm   = wid >> 1;          // 0..3 : 32-row M strip
    const int wn   = wid & 1;           // 0..1 : 32-col N strip
    const int m0   = blockIdx.x * MTILE;    // m fastest -> weight L2 reuse
    const int n0   = blockIdx.y * NTILE;
    const int kz   = blockIdx.z;            // k-split index
    // 64 slabs split 22/21/21 across kz = 0/1/2
    const int sk0    = (kz == 0) ? 0 : (22 + 21 * (kz - 1));
    const int nslabs = (kz == 0) ? 22 : 21;

    const __half* Abase = g_A + (size_t)m0 * K_DIM;

    float acc[2][4][4];
#pragma unroll
    for (int i = 0; i < 2; i++)
#pragma unroll
        for (int j = 0; j < 4; j++)
#pragma unroll
            for (int e = 0; e < 4; e++) acc[i][j][e] = 0.f;

    int4 wq[4];   // one W slab in flight

    // ---- prologue: A(0),A(1) committed; W(0) STS'd; wq=W(1) --------------
    ldg_w(wq, W, n0, sk0 + 0, tid);
    issue_A(Abase, (sk0 + 0) * KSLAB, smem, tid);
    issue_A(Abase, (sk0 + 1) * KSLAB, smem + STAGE_BYTES, tid);
    dequant_sts(wq, smem + W_OFF, tid);
    ldg_w(wq, W, n0, sk0 + 1, tid);

    // ---- main loop: 3-stage A pipeline, W staged one ahead ----------------
#pragma unroll 1
    for (int s = 0; s < nslabs; s++) {
        const uint32_t a_sm = smem + (s % STAGES) * STAGE_BYTES;
        const uint32_t w_sm = a_sm + W_OFF;

        if (s + 2 < nslabs)
            asm volatile("cp.async.wait_group 1;" ::: "memory");  // A(s) done
        else
            asm volatile("cp.async.wait_group 0;" ::: "memory");
        __syncthreads();   // stage s%3 ready; stage (s+2)%3 free (readers done)

        if (s + 1 < nslabs) {
            if (s + 2 < nslabs)
                issue_A(Abase, (sk0 + s + 2) * KSLAB,
                        smem + ((s + 2) % STAGES) * STAGE_BYTES, tid);
            dequant_sts(wq, smem + ((s + 1) % STAGES) * STAGE_BYTES + W_OFF, tid);
            if (s + 2 < nslabs)
                ldg_w(wq, W, n0, sk0 + s + 2, tid);
        }

        // compute slab s: 4 k-steps of 16
#pragma unroll
        for (int ks = 0; ks < 4; ks++) {
            const int chunk = ks * 2 + (lane >> 4);
            uint32_t a[2][4];
#pragma unroll
            for (int mt = 0; mt < 2; mt++) {
                int row = wm * 32 + mt * 16 + (lane & 15);
                ldsm_x4(a[mt][0], a[mt][1], a[mt][2], a[mt][3],
                        a_sm + SWZ(row * 128 + chunk * 16));
            }
            uint32_t b[4][2];
#pragma unroll
            for (int j = 0; j < 2; j++) {
                int row = wn * 32 + j * 16 + (lane & 15);
                uint32_t t0, t1, t2, t3;
                ldsm_x4(t0, t1, t2, t3, w_sm + SWZ(row * 128 + chunk * 16));
                b[j * 2 + 0][0] = t0;  b[j * 2 + 1][0] = t1;
                b[j * 2 + 0][1] = t2;  b[j * 2 + 1][1] = t3;
            }
#pragma unroll
            for (int mt = 0; mt < 2; mt++)
#pragma unroll
                for (int nt = 0; nt < 4; nt++)
                    mma16816(acc[mt][nt], a[mt], b[nt][0], b[nt][1]);
        }
    }

    // ---- epilogue: raw partial -> g_P[kz] --------------------------------
    float* Pbase = g_P + (size_t)kz * (M_DIM * N_DIM);
    const int ncb = n0 + wn * 32;
#pragma unroll
    for (int mt = 0; mt < 2; mt++) {
        int row = m0 + wm * 32 + mt * 16 + (lane >> 2);
#pragma unroll
        for (int nt = 0; nt < 4; nt++) {
            int col = ncb + nt * 8 + (lane & 3) * 2;
            float2 v0, v1;
            v0.x = acc[mt][nt][0];  v0.y = acc[mt][nt][1];
            v1.x = acc[mt][nt][2];  v1.y = acc[mt][nt][3];
            *reinterpret_cast<float2*>(Pbase + (size_t)row * N_DIM + col)       = v0;
            *reinterpret_cast<float2*>(Pbase + (size_t)(row + 8) * N_DIM + col) = v1;
        }
    }
}

// ------------------------------------------------------------------ reduction
// out = bias + scale * ((p0 + p1) + p2), fixed order -> deterministic
__global__ void reduce_kernel(const float* __restrict__ scale,
                              const float* __restrict__ bias,
                              float* __restrict__ out) {
    constexpr int N4     = N_DIM / 4;              // 2752
    constexpr int TOTAL4 = (M_DIM * N_DIM) / 4;    // 1409024
    int i = blockIdx.x * blockDim.x + threadIdx.x;
    if (i >= TOTAL4) return;

    const float4* P = reinterpret_cast<const float4*>(g_P);
    float4 s0 = P[i];
    float4 s1 = P[i + TOTAL4];
    float4 s2 = P[i + 2 * TOTAL4];
    float4 s;
    s.x = (s0.x + s1.x) + s2.x;
    s.y = (s0.y + s1.y) + s2.y;
    s.z = (s0.z + s1.z) + s2.z;
    s.w = (s0.w + s1.w) + s2.w;

    int nc = i % N4;
    float4 sc = reinterpret_cast<const float4*>(scale)[nc];
    float4 bi = reinterpret_cast<const float4*>(bias)[nc];
    float4 r;
    r.x = fmaf(sc.x, s.x, bi.x);
    r.y = fmaf(sc.y, s.y, bi.y);
    r.z = fmaf(sc.z, s.z, bi.z);
    r.w = fmaf(sc.w, s.w, bi.w);
    reinterpret_cast<float4*>(out)[i] = r;
}

// ------------------------------------------------------------------ launch
extern "C" void kernel_launch(void* const* d_in, const int* in_sizes, int n_in,
                              void* d_out, int out_size) {
    (void)in_sizes; (void)n_in; (void)out_size;
    const float* input = (const float*)d_in[0];
    const int4*  W     = (const int4*)d_in[1];
    const float* scale = (const float*)d_in[2];
    const float* bias  = (const float*)d_in[3];
    float* out = (float*)d_out;

    convert_A_kernel<<<(M_DIM * K_DIM / 4 + 255) / 256, 256>>>(input);

    cudaFuncSetAttribute(qlinear_hmma_kernel,
                         cudaFuncAttributeMaxDynamicSharedMemorySize, SMEM_BYTES);
    dim3 grid(M_DIM / MTILE, N_DIM / NTILE, KSPLIT);   // m fastest: W L2 reuse
    qlinear_hmma_kernel<<<grid, THREADS, SMEM_BYTES>>>(W);

    constexpr int TOTAL4 = (M_DIM * N_DIM) / 4;
    reduce_kernel<<<(TOTAL4 + 255) / 256, 256>>>(scale, bias, out);
}